// round 13
// baseline (speedup 1.0000x reference)
#include <cuda_runtime.h>
#include <cuda_fp16.h>
#include <math.h>
#include <stdint.h>

// ---------------------------------------------------------------------------
// CHI block on GB300 (sm_103 PTX => mma.sync HMMA path).
// R13: gemm_tc 128x128 tile, 2 CTAs/SM, 3-stage; launch index 3 = gemm_tc
// so the profiler finally captures it.
// ---------------------------------------------------------------------------

#define Bsz   8
#define Nseq  1024
#define Cdim  1024
#define HidD  4096
#define NH    16
#define HD    64
#define Mrows (Bsz * Nseq)           // 8192

typedef __half fp16;

// ---------------- scratch (static device globals; no allocs) ---------------
__device__ fp16 g_wT_hi[16u << 20];
__device__ fp16 g_xA_hi[(size_t)Mrows * Cdim];
__device__ fp16 g_xB_hi[(size_t)Mrows * Cdim];
__device__ fp16 g_q_hi [(size_t)Mrows * Cdim];
__device__ fp16 g_kv   [(size_t)Mrows * 2 * Cdim];
__device__ fp16 g_ao_hi[(size_t)Mrows * Cdim];
__device__ fp16 g_h_hi [(size_t)Mrows * HidD];
__device__ fp16 g_res16[(size_t)Mrows * Cdim];

// ------------------------------ PTX helpers --------------------------------
__device__ __forceinline__ uint32_t smem_u32(const void* p) {
    uint32_t a;
    asm("{ .reg .u64 t; cvta.to.shared.u64 t, %1; cvt.u32.u64 %0, t; }"
        : "=r"(a) : "l"(p));
    return a;
}

__device__ __forceinline__ void cp16(uint32_t dst, const void* src) {
    asm volatile("cp.async.cg.shared.global [%0], [%1], 16;\n"
                 :: "r"(dst), "l"(src) : "memory");
}
#define CP_COMMIT() asm volatile("cp.async.commit_group;\n" ::: "memory")
#define CP_WAIT1()  asm volatile("cp.async.wait_group 1;\n" ::: "memory")
#define CP_WAIT0()  asm volatile("cp.async.wait_group 0;\n" ::: "memory")

__device__ __forceinline__ void ldsm4(uint32_t (&r)[4], uint32_t addr) {
    asm volatile("ldmatrix.sync.aligned.m8n8.x4.shared.b16 {%0,%1,%2,%3}, [%4];"
        : "=r"(r[0]), "=r"(r[1]), "=r"(r[2]), "=r"(r[3]) : "r"(addr));
}
__device__ __forceinline__ void ldsm4t(uint32_t (&r)[4], uint32_t addr) {
    asm volatile("ldmatrix.sync.aligned.m8n8.x4.trans.shared.b16 {%0,%1,%2,%3}, [%4];"
        : "=r"(r[0]), "=r"(r[1]), "=r"(r[2]), "=r"(r[3]) : "r"(addr));
}

__device__ __forceinline__ void mma16816(float (&d)[4], const uint32_t (&a)[4],
                                         uint32_t b0, uint32_t b1) {
    asm volatile(
        "mma.sync.aligned.m16n8k16.row.col.f32.f16.f16.f32 "
        "{%0,%1,%2,%3}, {%4,%5,%6,%7}, {%8,%9}, {%0,%1,%2,%3};"
        : "+f"(d[0]), "+f"(d[1]), "+f"(d[2]), "+f"(d[3])
        : "r"(a[0]), "r"(a[1]), "r"(a[2]), "r"(a[3]), "r"(b0), "r"(b1));
}

__device__ __forceinline__ uint32_t pack_h2(float a, float b) {
    __half2 v = __floats2half2_rn(a, b);
    return *reinterpret_cast<uint32_t*>(&v);
}

// ------------------------------ LayerNorm ----------------------------------
__global__ __launch_bounds__(256) void ln_kernel(
    const float* __restrict__ x, const float* __restrict__ gma,
    const float* __restrict__ bta, fp16* __restrict__ ohi)
{
    int row = blockIdx.x;
    int t   = threadIdx.x;
    const float4* xr = (const float4*)(x + (size_t)row * Cdim);
    float4 v = xr[t];
    float s  = v.x + v.y + v.z + v.w;
    float s2 = v.x*v.x + v.y*v.y + v.z*v.z + v.w*v.w;

    __shared__ float sa[8], sb_[8];
    #pragma unroll
    for (int o = 16; o > 0; o >>= 1) {
        s  += __shfl_down_sync(0xffffffffu, s,  o);
        s2 += __shfl_down_sync(0xffffffffu, s2, o);
    }
    int w = t >> 5, l = t & 31;
    if (l == 0) { sa[w] = s; sb_[w] = s2; }
    __syncthreads();
    if (w == 0) {
        s  = (l < 8) ? sa[l] : 0.f;
        s2 = (l < 8) ? sb_[l] : 0.f;
        #pragma unroll
        for (int o = 4; o > 0; o >>= 1) {
            s  += __shfl_down_sync(0xffffffffu, s,  o);
            s2 += __shfl_down_sync(0xffffffffu, s2, o);
        }
        if (l == 0) { sa[0] = s; sb_[0] = s2; }
    }
    __syncthreads();
    float mean = sa[0] * (1.0f / Cdim);
    float var  = sb_[0] * (1.0f / Cdim) - mean * mean;
    float r    = rsqrtf(var + 1e-5f);

    float4 g4 = ((const float4*)gma)[t];
    float4 b4 = ((const float4*)bta)[t];
    float o0 = (v.x - mean) * r * g4.x + b4.x;
    float o1 = (v.y - mean) * r * g4.y + b4.y;
    float o2 = (v.z - mean) * r * g4.z + b4.z;
    float o3 = (v.w - mean) * r * g4.w + b4.w;

    size_t idx = (size_t)row * Cdim + t * 4;
    *(__half2*)(ohi + idx)     = __floats2half2_rn(o0, o1);
    *(__half2*)(ohi + idx + 2) = __floats2half2_rn(o2, o3);
}

// fp16-input LayerNorm
__global__ __launch_bounds__(256) void ln16_kernel(
    const fp16* __restrict__ x, const float* __restrict__ gma,
    const float* __restrict__ bta, fp16* __restrict__ ohi)
{
    int row = blockIdx.x;
    int t   = threadIdx.x;
    const __half2* xr = (const __half2*)(x + (size_t)row * Cdim);
    __half2 h0 = xr[2 * t], h1 = xr[2 * t + 1];
    float v0 = __low2float(h0), v1 = __high2float(h0);
    float v2 = __low2float(h1), v3 = __high2float(h1);
    float s  = v0 + v1 + v2 + v3;
    float s2 = v0*v0 + v1*v1 + v2*v2 + v3*v3;

    __shared__ float sa[8], sb_[8];
    #pragma unroll
    for (int o = 16; o > 0; o >>= 1) {
        s  += __shfl_down_sync(0xffffffffu, s,  o);
        s2 += __shfl_down_sync(0xffffffffu, s2, o);
    }
    int w = t >> 5, l = t & 31;
    if (l == 0) { sa[w] = s; sb_[w] = s2; }
    __syncthreads();
    if (w == 0) {
        s  = (l < 8) ? sa[l] : 0.f;
        s2 = (l < 8) ? sb_[l] : 0.f;
        #pragma unroll
        for (int o = 4; o > 0; o >>= 1) {
            s  += __shfl_down_sync(0xffffffffu, s,  o);
            s2 += __shfl_down_sync(0xffffffffu, s2, o);
        }
        if (l == 0) { sa[0] = s; sb_[0] = s2; }
    }
    __syncthreads();
    float mean = sa[0] * (1.0f / Cdim);
    float var  = sb_[0] * (1.0f / Cdim) - mean * mean;
    float r    = rsqrtf(var + 1e-5f);

    float4 g4 = ((const float4*)gma)[t];
    float4 b4 = ((const float4*)bta)[t];
    float o0 = (v0 - mean) * r * g4.x + b4.x;
    float o1 = (v1 - mean) * r * g4.y + b4.y;
    float o2 = (v2 - mean) * r * g4.z + b4.z;
    float o3 = (v3 - mean) * r * g4.w + b4.w;

    size_t idx = (size_t)row * Cdim + t * 4;
    *(__half2*)(ohi + idx)     = __floats2half2_rn(o0, o1);
    *(__half2*)(ohi + idx + 2) = __floats2half2_rn(o2, o3);
}

// ----------------------- weight transpose (fp16 hi) ------------------------
__global__ __launch_bounds__(256) void wconv_kernel(
    const float* __restrict__ W, fp16* __restrict__ Whi, int K, int N)
{
    __shared__ float tile[32][33];
    int n0 = blockIdx.x * 32, k0 = blockIdx.y * 32;
    int tx = threadIdx.x & 31, ty = threadIdx.x >> 5;
    #pragma unroll
    for (int i = 0; i < 4; i++)
        tile[ty + i * 8][tx] = W[(size_t)(k0 + ty + i * 8) * N + n0 + tx];
    __syncthreads();
    #pragma unroll
    for (int i = 0; i < 4; i++) {
        int r = ty + i * 8;
        Whi[(size_t)(n0 + r) * K + k0 + tx] = __float2half_rn(tile[tx][r]);
    }
}

__global__ __launch_bounds__(256) void wconv2_kernel(
    const float* __restrict__ W1, const float* __restrict__ W2,
    fp16* __restrict__ D1, fp16* __restrict__ D2, int K, int N)
{
    const float* W = blockIdx.z ? W2 : W1;
    fp16* D = blockIdx.z ? D2 : D1;
    __shared__ float tile[32][33];
    int n0 = blockIdx.x * 32, k0 = blockIdx.y * 32;
    int tx = threadIdx.x & 31, ty = threadIdx.x >> 5;
    #pragma unroll
    for (int i = 0; i < 4; i++)
        tile[ty + i * 8][tx] = W[(size_t)(k0 + ty + i * 8) * N + n0 + tx];
    __syncthreads();
    #pragma unroll
    for (int i = 0; i < 4; i++) {
        int r = ty + i * 8;
        D[(size_t)(n0 + r) * K + k0 + tx] = __float2half_rn(tile[tx][r]);
    }
}

// --------------------------- mma.sync GEMM ---------------------------------
// C[M,N] = A_hi[M,K] @ B_hi^T,  B stored [N,K].  fp16, single pass.
// 128x128 CTA tile, BK=64, 8 warps (2m x 4n), warp tile 64x32,
// 3-stage cp.async, one barrier/iter, 2 CTAs per SM.
#define GF_BIAS  1
#define GF_RES   2
#define GF_GELU  4
#define GF_HI    16
#define GF_RES16 32

#define G_STRIDE_B 144u        // 64 fp16 (128B) + 16B pad
#define G_A_B      18432u      // 128 rows * 144B
#define G_STAGE_B  36864u      // Ahi + Bhi (128 rows each)
#define GEMM_SMEM  (3 * 36864) // 110592

__global__ __launch_bounds__(256, 2) void gemm_tc(
    const fp16* __restrict__ Ahi, const fp16* __restrict__ Bhi,
    const float* __restrict__ bias, const float* __restrict__ res,
    const fp16* __restrict__ resH,
    float* __restrict__ outF, fp16* __restrict__ outHi,
    int M, int N, int K, int flags)
{
    extern __shared__ char smem[];
    const uint32_t sb = smem_u32(smem);
    const int t = threadIdx.x, lane = t & 31, wid = t >> 5;
    const int bn = blockIdx.x, bm = blockIdx.y;
    const int wm = wid >> 2, wn = wid & 3;   // 2m x 4n warps

    const fp16* srcA = Ahi + (size_t)(bm * 128) * K;
    const fp16* srcB = Bhi + (size_t)(bn * 128) * K;

    auto load_stage = [&](int s) {
        uint32_t base = sb + (uint32_t)(s % 3) * G_STAGE_B;
        int k0 = s << 6;
        #pragma unroll
        for (int i = 0; i < 8; i++) {
            int idx = t + (i << 8);
            const fp16* src;
            uint32_t off;
            int cid;
            if (idx < 1024) { cid = idx;        src = srcA; off = 0; }
            else            { cid = idx - 1024; src = srcB; off = G_A_B; }
            int row = cid >> 3, c = cid & 7;
            cp16(base + off + (uint32_t)row * G_STRIDE_B + (uint32_t)c * 16u,
                 src + (size_t)row * K + k0 + c * 8);
        }
        CP_COMMIT();
    };

    float acc[4][4][4];
    #pragma unroll
    for (int mi = 0; mi < 4; mi++)
        #pragma unroll
        for (int ni = 0; ni < 4; ni++)
            #pragma unroll
            for (int j = 0; j < 4; j++) acc[mi][ni][j] = 0.f;

    load_stage(0);
    load_stage(1);
    const int S = K >> 6;
    const uint32_t lrow = (uint32_t)(lane & 15);
    const uint32_t lc16 = (uint32_t)(lane >> 4) * 16u;
    const uint32_t aoff = ((uint32_t)(wm * 64) + lrow) * G_STRIDE_B + lc16;
    const uint32_t boff = ((uint32_t)(wn * 32) + lrow) * G_STRIDE_B + lc16;

    for (int s = 0; s < S; s++) {
        if (s + 1 < S) { CP_WAIT1(); }
        else           { CP_WAIT0(); }
        __syncthreads();
        uint32_t base = sb + (uint32_t)(s % 3) * G_STAGE_B;
        #pragma unroll
        for (int k16 = 0; k16 < 4; k16++) {
            uint32_t ko = (uint32_t)k16 * 32u;
            uint32_t ah[4][4], bf[2][4];
            #pragma unroll
            for (int f = 0; f < 4; f++)
                ldsm4(ah[f], base + aoff + (uint32_t)f * 16u * G_STRIDE_B + ko);
            #pragma unroll
            for (int g = 0; g < 2; g++)
                ldsm4(bf[g], base + G_A_B + boff + (uint32_t)g * 16u * G_STRIDE_B + ko);
            #pragma unroll
            for (int mi = 0; mi < 4; mi++)
                #pragma unroll
                for (int ni = 0; ni < 4; ni++)
                    mma16816(acc[mi][ni], ah[mi],
                             bf[ni >> 1][ni & 1], bf[ni >> 1][2 + (ni & 1)]);
        }
        if (s + 2 < S) load_stage(s + 2);
    }

    // ------------------------------ epilogue -------------------------------
    const int r0 = bm * 128 + wm * 64 + (lane >> 2);
    const int c0 = bn * 128 + wn * 32 + (lane & 3) * 2;
    #pragma unroll
    for (int mi = 0; mi < 4; mi++)
        #pragma unroll
        for (int rh = 0; rh < 2; rh++) {
            int row = r0 + mi * 16 + rh * 8;
            #pragma unroll
            for (int ni = 0; ni < 4; ni++) {
                int col = c0 + ni * 8;
                float v0 = acc[mi][ni][2 * rh];
                float v1 = acc[mi][ni][2 * rh + 1];
                if (flags & GF_BIAS) { v0 += bias[col]; v1 += bias[col + 1]; }
                if (flags & GF_GELU) {
                    v0 = 0.5f * v0 * (1.0f + erff(v0 * 0.70710678118654752f));
                    v1 = 0.5f * v1 * (1.0f + erff(v1 * 0.70710678118654752f));
                }
                if (flags & GF_RES) {
                    const float* rp = res + (size_t)row * N + col;
                    v0 += rp[0]; v1 += rp[1];
                }
                if (flags & GF_RES16) {
                    __half2 rv = *(const __half2*)(resH + (size_t)row * N + col);
                    v0 += __low2float(rv); v1 += __high2float(rv);
                }
                if (flags & GF_HI) {
                    *(__half2*)(outHi + (size_t)row * N + col) =
                        __floats2half2_rn(v0, v1);
                } else {
                    float2* po = (float2*)(outF + (size_t)row * N + col);
                    *po = make_float2(v0, v1);
                }
            }
        }
}

// --------------------- tensor-core flash attention -------------------------
#define A_STRIDE_B 144u
#define A_OP_B     9216u
#define A_STAGE_B  18432u
#define A_Q_B      9216u
#define ATTN_SMEM  (9216 + 2 * 18432)
#define KVS        (2 * Cdim)

__global__ __launch_bounds__(128) void attn_tc(
    const fp16* __restrict__ qhi, const fp16* __restrict__ kv,
    fp16* __restrict__ ohi)
{
    extern __shared__ char smem[];
    const uint32_t sb = smem_u32(smem);
    const int b = blockIdx.z, h = blockIdx.y, qt = blockIdx.x;
    const int t = threadIdx.x, lane = t & 31, wid = t >> 5;

    const size_t qrow0 = (size_t)(b * Nseq + qt * 64);
    const fp16* gq = qhi + qrow0 * Cdim + h * HD;
    const size_t krow0 = (size_t)b * Nseq;
    const fp16* gk = kv + krow0 * KVS + h * HD;
    const fp16* gv = kv + krow0 * KVS + Cdim + h * HD;

    #pragma unroll
    for (int i = 0; i < 4; i++) {
        int idx = t + (i << 7);
        int row = idx >> 3, c = idx & 7;
        cp16(sb + (uint32_t)row * A_STRIDE_B + (uint32_t)c * 16u,
             gq + (size_t)row * Cdim + c * 8);
    }
    CP_COMMIT();

    auto load_kv = [&](int kt) {
        uint32_t base = sb + A_Q_B + (uint32_t)(kt & 1) * A_STAGE_B;
        #pragma unroll
        for (int i = 0; i < 8; i++) {
            int idx = t + (i << 7);
            int op = idx >> 9, cid = idx & 511;
            int row = cid >> 3, c = cid & 7;
            const fp16* src = op ? gv : gk;
            cp16(base + (uint32_t)op * A_OP_B + (uint32_t)row * A_STRIDE_B
                      + (uint32_t)c * 16u,
                 src + (size_t)(kt * 64 + row) * KVS + c * 8);
        }
        CP_COMMIT();
    };

    load_kv(0);

    const uint32_t lrow = (uint32_t)(lane & 15);
    const uint32_t lc16 = (uint32_t)(lane >> 4) * 16u;

    uint32_t qh[4][4];
    float m_[2] = { -1e30f, -1e30f }, l_[2] = { 0.f, 0.f };
    float oacc[8][4];
    #pragma unroll
    for (int d = 0; d < 8; d++)
        #pragma unroll
        for (int j = 0; j < 4; j++) oacc[d][j] = 0.f;

    for (int kt = 0; kt < 16; kt++) {
        if (kt + 1 < 16) { load_kv(kt + 1); CP_WAIT1(); }
        else             { CP_WAIT0(); }
        __syncthreads();
        if (kt == 0) {
            uint32_t qoff = ((uint32_t)(wid * 16) + lrow) * A_STRIDE_B + lc16;
            #pragma unroll
            for (int k16 = 0; k16 < 4; k16++)
                ldsm4(qh[k16], sb + qoff + (uint32_t)k16 * 32u);
        }
        uint32_t base = sb + A_Q_B + (uint32_t)(kt & 1) * A_STAGE_B;

        // ---- S = Q K^T ----
        float sacc[8][4];
        #pragma unroll
        for (int ni = 0; ni < 8; ni++)
            #pragma unroll
            for (int j = 0; j < 4; j++) sacc[ni][j] = 0.f;
        uint32_t koff = lrow * A_STRIDE_B + lc16;
        #pragma unroll
        for (int k16 = 0; k16 < 4; k16++) {
            uint32_t kb[4][4];
            #pragma unroll
            for (int g = 0; g < 4; g++)
                ldsm4(kb[g], base + koff + (uint32_t)g * 16u * A_STRIDE_B
                             + (uint32_t)k16 * 32u);
            #pragma unroll
            for (int ni = 0; ni < 8; ni++)
                mma16816(sacc[ni], qh[k16],
                         kb[ni >> 1][ni & 1], kb[ni >> 1][2 + (ni & 1)]);
        }
        #pragma unroll
        for (int ni = 0; ni < 8; ni++)
            #pragma unroll
            for (int j = 0; j < 4; j++) sacc[ni][j] *= 0.125f;

        // ---- online softmax ----
        float corr[2];
        #pragma unroll
        for (int rh = 0; rh < 2; rh++) {
            float mx = m_[rh];
            #pragma unroll
            for (int ni = 0; ni < 8; ni++) {
                mx = fmaxf(mx, sacc[ni][2 * rh]);
                mx = fmaxf(mx, sacc[ni][2 * rh + 1]);
            }
            mx = fmaxf(mx, __shfl_xor_sync(0xffffffffu, mx, 1));
            mx = fmaxf(mx, __shfl_xor_sync(0xffffffffu, mx, 2));
            float c = __expf(m_[rh] - mx);
            m_[rh] = mx;
            float sum = 0.f;
            #pragma unroll
            for (int ni = 0; ni < 8; ni++) {
                float p0 = __expf(sacc[ni][2 * rh] - mx);
                float p1 = __expf(sacc[ni][2 * rh + 1] - mx);
                sacc[ni][2 * rh] = p0; sacc[ni][2 * rh + 1] = p1;
                sum += p0 + p1;
            }
            sum += __shfl_xor_sync(0xffffffffu, sum, 1);
            sum += __shfl_xor_sync(0xffffffffu, sum, 2);
            l_[rh] = l_[rh] * c + sum;
            corr[rh] = c;
        }
        #pragma unroll
        for (int d = 0; d < 8; d++) {
            oacc[d][0] *= corr[0]; oacc[d][1] *= corr[0];
            oacc[d][2] *= corr[1]; oacc[d][3] *= corr[1];
        }

        // ---- P -> fragments ----
        uint32_t pa[4][4];
        #pragma unroll
        for (int k16 = 0; k16 < 4; k16++) {
            pa[k16][0] = pack_h2(sacc[2*k16][0],   sacc[2*k16][1]);
            pa[k16][1] = pack_h2(sacc[2*k16][2],   sacc[2*k16][3]);
            pa[k16][2] = pack_h2(sacc[2*k16+1][0], sacc[2*k16+1][1]);
            pa[k16][3] = pack_h2(sacc[2*k16+1][2], sacc[2*k16+1][3]);
        }

        // ---- O += P V ----
        #pragma unroll
        for (int k16 = 0; k16 < 4; k16++) {
            uint32_t vh[4][4];
            uint32_t vrow = ((uint32_t)(k16 * 16) + lrow) * A_STRIDE_B + lc16;
            #pragma unroll
            for (int dblk = 0; dblk < 4; dblk++)
                ldsm4t(vh[dblk], base + A_OP_B + vrow + (uint32_t)dblk * 32u);
            #pragma unroll
            for (int dblk = 0; dblk < 4; dblk++)
                #pragma unroll
                for (int sub = 0; sub < 2; sub++)
                    mma16816(oacc[dblk * 2 + sub], pa[k16],
                             vh[dblk][2*sub], vh[dblk][2*sub+1]);
        }
        __syncthreads();
    }

    // ---- epilogue ----
    float inv[2] = { 1.0f / l_[0], 1.0f / l_[1] };
    const size_t orow = qrow0 + wid * 16 + (lane >> 2);
    const int c0 = h * HD + (lane & 3) * 2;
    #pragma unroll
    for (int di = 0; di < 8; di++)
        #pragma unroll
        for (int rh = 0; rh < 2; rh++) {
            size_t row = orow + rh * 8;
            int col = c0 + di * 8;
            float v0 = oacc[di][2 * rh]     * inv[rh];
            float v1 = oacc[di][2 * rh + 1] * inv[rh];
            *(__half2*)(ohi + row * Cdim + col) = __floats2half2_rn(v0, v1);
        }
}

// ------------------------------- launch ------------------------------------
extern "C" void kernel_launch(void* const* d_in, const int* in_sizes, int n_in,
                              void* d_out, int out_size)
{
    const float* x1     = (const float*)d_in[0];
    const float* x2     = (const float*)d_in[1];
    const float* x3     = (const float*)d_in[2];
    const float* ln11_g = (const float*)d_in[3];
    const float* ln11_b = (const float*)d_in[4];
    const float* ln12_g = (const float*)d_in[5];
    const float* ln12_b = (const float*)d_in[6];
    const float* ln21_g = (const float*)d_in[7];
    const float* ln21_b = (const float*)d_in[8];
    const float* ln23_g = (const float*)d_in[9];
    const float* ln23_b = (const float*)d_in[10];
    const float* ln2_g  = (const float*)d_in[11];
    const float* ln2_b  = (const float*)d_in[12];
    const float* a1_wq  = (const float*)d_in[13];
    const float* a1_wk  = (const float*)d_in[14];
    const float* a1_wv  = (const float*)d_in[15];
    const float* a1_wp  = (const float*)d_in[16];
    const float* a1_bp  = (const float*)d_in[17];
    const float* a2_wq  = (const float*)d_in[18];
    const float* a2_wk  = (const float*)d_in[19];
    const float* a2_wv  = (const float*)d_in[20];
    const float* a2_wp  = (const float*)d_in[21];
    const float* a2_bp  = (const float*)d_in[22];
    const float* fc1_w  = (const float*)d_in[23];
    const float* fc1_b  = (const float*)d_in[24];
    const float* fc2_w  = (const float*)d_in[25];
    const float* fc2_b  = (const float*)d_in[26];
    float* out = (float*)d_out;

    fp16 *wT_hi, *xA_hi, *xB_hi, *q_hi, *kv, *ao_hi, *h_hi, *res16;
    cudaGetSymbolAddress((void**)&wT_hi, g_wT_hi);
    cudaGetSymbolAddress((void**)&xA_hi, g_xA_hi);
    cudaGetSymbolAddress((void**)&xB_hi, g_xB_hi);
    cudaGetSymbolAddress((void**)&q_hi,  g_q_hi);
    cudaGetSymbolAddress((void**)&kv,    g_kv);
    cudaGetSymbolAddress((void**)&ao_hi, g_ao_hi);
    cudaGetSymbolAddress((void**)&h_hi,  g_h_hi);
    cudaGetSymbolAddress((void**)&res16, g_res16);

    cudaFuncSetAttribute(gemm_tc,
                         cudaFuncAttributeMaxDynamicSharedMemorySize, GEMM_SMEM);
    cudaFuncSetAttribute(attn_tc,
                         cudaFuncAttributeMaxDynamicSharedMemorySize, ATTN_SMEM);

    const size_t MEG = 1u << 20;
    dim3 wgC(Cdim / 32, Cdim / 32);
    dim3 wgC2(Cdim / 32, Cdim / 32, 2);
    dim3 gC(Cdim / 128, Mrows / 128);        // (8, 64)
    dim3 gKV(2 * Cdim / 128, Mrows / 128);   // (16, 64)
    dim3 gH(HidD / 128, Mrows / 128);        // (32, 64)
    dim3 ga(Nseq / 64, NH, Bsz);             // (16, 16, 8)

    // ---- branch 1 (launch index 3 == gemm_tc for the profiler) ----
    ln_kernel<<<Mrows, 256>>>(x1, ln11_g, ln11_b, xA_hi);                  // 0
    ln_kernel<<<Mrows, 256>>>(x2, ln12_g, ln12_b, xB_hi);                  // 1
    wconv_kernel<<<wgC, 256>>>(a1_wq, wT_hi + 0*MEG, Cdim, Cdim);          // 2
    gemm_tc<<<gC, 256, GEMM_SMEM>>>(xA_hi, wT_hi + 0*MEG,                  // 3 <- ncu
        nullptr, nullptr, nullptr, nullptr, q_hi, Mrows, Cdim, Cdim, GF_HI);
    wconv2_kernel<<<wgC2, 256>>>(a1_wk, a1_wv,
        wT_hi + 1*MEG, wT_hi + 2*MEG, Cdim, Cdim);                         // 4
    gemm_tc<<<gKV, 256, GEMM_SMEM>>>(xB_hi, wT_hi + 1*MEG,                 // 5
        nullptr, nullptr, nullptr, nullptr, kv, Mrows, 2 * Cdim, Cdim, GF_HI);
    attn_tc<<<ga, 128, ATTN_SMEM>>>(q_hi, kv, ao_hi);
    wconv_kernel<<<wgC, 256>>>(a1_wp, wT_hi + 3*MEG, Cdim, Cdim);
    gemm_tc<<<gC, 256, GEMM_SMEM>>>(ao_hi, wT_hi + 3*MEG,
        a1_bp, x1, nullptr, nullptr, res16, Mrows, Cdim, Cdim,
        GF_BIAS | GF_RES | GF_HI);

    // ---- remaining weight conversions ----
    wconv_kernel<<<wgC, 256>>>(a2_wq, wT_hi + 4*MEG, Cdim, Cdim);
    wconv2_kernel<<<wgC2, 256>>>(a2_wk, a2_wv,
        wT_hi + 5*MEG, wT_hi + 6*MEG, Cdim, Cdim);
    wconv_kernel<<<wgC, 256>>>(a2_wp, wT_hi + 7*MEG, Cdim, Cdim);
    wconv_kernel<<<dim3(HidD / 32, Cdim / 32), 256>>>(
        fc1_w, wT_hi + 8*MEG, Cdim, HidD);
    wconv_kernel<<<dim3(Cdim / 32, HidD / 32), 256>>>(
        fc2_w, wT_hi + 12*MEG, HidD, Cdim);

    // ---- branch 2 ----
    ln_kernel<<<Mrows, 256>>>(x1, ln21_g, ln21_b, xA_hi);
    ln_kernel<<<Mrows, 256>>>(x3, ln23_g, ln23_b, xB_hi);
    gemm_tc<<<gC, 256, GEMM_SMEM>>>(xA_hi, wT_hi + 4*MEG,
        nullptr, nullptr, nullptr, nullptr, q_hi, Mrows, Cdim, Cdim, GF_HI);
    gemm_tc<<<gKV, 256, GEMM_SMEM>>>(xB_hi, wT_hi + 5*MEG,
        nullptr, nullptr, nullptr, nullptr, kv, Mrows, 2 * Cdim, Cdim, GF_HI);
    attn_tc<<<ga, 128, ATTN_SMEM>>>(q_hi, kv, ao_hi);
    gemm_tc<<<gC, 256, GEMM_SMEM>>>(ao_hi, wT_hi + 7*MEG,
        a2_bp, nullptr, res16, nullptr, res16, Mrows, Cdim, Cdim,
        GF_BIAS | GF_RES16 | GF_HI);

    // ---- MLP ----
    ln16_kernel<<<Mrows, 256>>>(res16, ln2_g, ln2_b, xA_hi);
    gemm_tc<<<gH, 256, GEMM_SMEM>>>(xA_hi, wT_hi + 8*MEG,
        fc1_b, nullptr, nullptr, nullptr, h_hi, Mrows, HidD, Cdim,
        GF_BIAS | GF_GELU | GF_HI);
    gemm_tc<<<gC, 256, GEMM_SMEM>>>(h_hi, wT_hi + 12*MEG,
        fc2_b, nullptr, res16, out, nullptr, Mrows, Cdim, HidD,
        GF_BIAS | GF_RES16);
}

// round 14
// speedup vs baseline: 1.4173x; 1.4173x over previous
#include <cuda_runtime.h>
#include <cuda_fp16.h>
#include <math.h>
#include <stdint.h>

// ---------------------------------------------------------------------------
// CHI block on GB300 (sm_103 PTX => mma.sync HMMA path).
// R14: back to 128x256 tile / 4-stage / single barrier (R12 = 1403us), plus
// intra-stage ldsm fragment double-buffering to hide LDS latency under MMA.
// ---------------------------------------------------------------------------

#define Bsz   8
#define Nseq  1024
#define Cdim  1024
#define HidD  4096
#define NH    16
#define HD    64
#define Mrows (Bsz * Nseq)           // 8192

typedef __half fp16;

// ---------------- scratch (static device globals; no allocs) ---------------
__device__ fp16 g_wT_hi[16u << 20];
__device__ fp16 g_xA_hi[(size_t)Mrows * Cdim];
__device__ fp16 g_xB_hi[(size_t)Mrows * Cdim];
__device__ fp16 g_q_hi [(size_t)Mrows * Cdim];
__device__ fp16 g_kv   [(size_t)Mrows * 2 * Cdim];
__device__ fp16 g_ao_hi[(size_t)Mrows * Cdim];
__device__ fp16 g_h_hi [(size_t)Mrows * HidD];
__device__ fp16 g_res16[(size_t)Mrows * Cdim];

// ------------------------------ PTX helpers --------------------------------
__device__ __forceinline__ uint32_t smem_u32(const void* p) {
    uint32_t a;
    asm("{ .reg .u64 t; cvta.to.shared.u64 t, %1; cvt.u32.u64 %0, t; }"
        : "=r"(a) : "l"(p));
    return a;
}

__device__ __forceinline__ void cp16(uint32_t dst, const void* src) {
    asm volatile("cp.async.cg.shared.global [%0], [%1], 16;\n"
                 :: "r"(dst), "l"(src) : "memory");
}
#define CP_COMMIT() asm volatile("cp.async.commit_group;\n" ::: "memory")
#define CP_WAIT2()  asm volatile("cp.async.wait_group 2;\n" ::: "memory")
#define CP_WAIT1()  asm volatile("cp.async.wait_group 1;\n" ::: "memory")
#define CP_WAIT0()  asm volatile("cp.async.wait_group 0;\n" ::: "memory")

__device__ __forceinline__ void ldsm4(uint32_t (&r)[4], uint32_t addr) {
    asm volatile("ldmatrix.sync.aligned.m8n8.x4.shared.b16 {%0,%1,%2,%3}, [%4];"
        : "=r"(r[0]), "=r"(r[1]), "=r"(r[2]), "=r"(r[3]) : "r"(addr));
}
__device__ __forceinline__ void ldsm4t(uint32_t (&r)[4], uint32_t addr) {
    asm volatile("ldmatrix.sync.aligned.m8n8.x4.trans.shared.b16 {%0,%1,%2,%3}, [%4];"
        : "=r"(r[0]), "=r"(r[1]), "=r"(r[2]), "=r"(r[3]) : "r"(addr));
}

__device__ __forceinline__ void mma16816(float (&d)[4], const uint32_t (&a)[4],
                                         uint32_t b0, uint32_t b1) {
    asm volatile(
        "mma.sync.aligned.m16n8k16.row.col.f32.f16.f16.f32 "
        "{%0,%1,%2,%3}, {%4,%5,%6,%7}, {%8,%9}, {%0,%1,%2,%3};"
        : "+f"(d[0]), "+f"(d[1]), "+f"(d[2]), "+f"(d[3])
        : "r"(a[0]), "r"(a[1]), "r"(a[2]), "r"(a[3]), "r"(b0), "r"(b1));
}

__device__ __forceinline__ uint32_t pack_h2(float a, float b) {
    __half2 v = __floats2half2_rn(a, b);
    return *reinterpret_cast<uint32_t*>(&v);
}

// ------------------------------ LayerNorm ----------------------------------
__global__ __launch_bounds__(256) void ln_kernel(
    const float* __restrict__ x, const float* __restrict__ gma,
    const float* __restrict__ bta, fp16* __restrict__ ohi)
{
    int row = blockIdx.x;
    int t   = threadIdx.x;
    const float4* xr = (const float4*)(x + (size_t)row * Cdim);
    float4 v = xr[t];
    float s  = v.x + v.y + v.z + v.w;
    float s2 = v.x*v.x + v.y*v.y + v.z*v.z + v.w*v.w;

    __shared__ float sa[8], sb_[8];
    #pragma unroll
    for (int o = 16; o > 0; o >>= 1) {
        s  += __shfl_down_sync(0xffffffffu, s,  o);
        s2 += __shfl_down_sync(0xffffffffu, s2, o);
    }
    int w = t >> 5, l = t & 31;
    if (l == 0) { sa[w] = s; sb_[w] = s2; }
    __syncthreads();
    if (w == 0) {
        s  = (l < 8) ? sa[l] : 0.f;
        s2 = (l < 8) ? sb_[l] : 0.f;
        #pragma unroll
        for (int o = 4; o > 0; o >>= 1) {
            s  += __shfl_down_sync(0xffffffffu, s,  o);
            s2 += __shfl_down_sync(0xffffffffu, s2, o);
        }
        if (l == 0) { sa[0] = s; sb_[0] = s2; }
    }
    __syncthreads();
    float mean = sa[0] * (1.0f / Cdim);
    float var  = sb_[0] * (1.0f / Cdim) - mean * mean;
    float r    = rsqrtf(var + 1e-5f);

    float4 g4 = ((const float4*)gma)[t];
    float4 b4 = ((const float4*)bta)[t];
    float o0 = (v.x - mean) * r * g4.x + b4.x;
    float o1 = (v.y - mean) * r * g4.y + b4.y;
    float o2 = (v.z - mean) * r * g4.z + b4.z;
    float o3 = (v.w - mean) * r * g4.w + b4.w;

    size_t idx = (size_t)row * Cdim + t * 4;
    *(__half2*)(ohi + idx)     = __floats2half2_rn(o0, o1);
    *(__half2*)(ohi + idx + 2) = __floats2half2_rn(o2, o3);
}

// fp16-input LayerNorm
__global__ __launch_bounds__(256) void ln16_kernel(
    const fp16* __restrict__ x, const float* __restrict__ gma,
    const float* __restrict__ bta, fp16* __restrict__ ohi)
{
    int row = blockIdx.x;
    int t   = threadIdx.x;
    const __half2* xr = (const __half2*)(x + (size_t)row * Cdim);
    __half2 h0 = xr[2 * t], h1 = xr[2 * t + 1];
    float v0 = __low2float(h0), v1 = __high2float(h0);
    float v2 = __low2float(h1), v3 = __high2float(h1);
    float s  = v0 + v1 + v2 + v3;
    float s2 = v0*v0 + v1*v1 + v2*v2 + v3*v3;

    __shared__ float sa[8], sb_[8];
    #pragma unroll
    for (int o = 16; o > 0; o >>= 1) {
        s  += __shfl_down_sync(0xffffffffu, s,  o);
        s2 += __shfl_down_sync(0xffffffffu, s2, o);
    }
    int w = t >> 5, l = t & 31;
    if (l == 0) { sa[w] = s; sb_[w] = s2; }
    __syncthreads();
    if (w == 0) {
        s  = (l < 8) ? sa[l] : 0.f;
        s2 = (l < 8) ? sb_[l] : 0.f;
        #pragma unroll
        for (int o = 4; o > 0; o >>= 1) {
            s  += __shfl_down_sync(0xffffffffu, s,  o);
            s2 += __shfl_down_sync(0xffffffffu, s2, o);
        }
        if (l == 0) { sa[0] = s; sb_[0] = s2; }
    }
    __syncthreads();
    float mean = sa[0] * (1.0f / Cdim);
    float var  = sb_[0] * (1.0f / Cdim) - mean * mean;
    float r    = rsqrtf(var + 1e-5f);

    float4 g4 = ((const float4*)gma)[t];
    float4 b4 = ((const float4*)bta)[t];
    float o0 = (v0 - mean) * r * g4.x + b4.x;
    float o1 = (v1 - mean) * r * g4.y + b4.y;
    float o2 = (v2 - mean) * r * g4.z + b4.z;
    float o3 = (v3 - mean) * r * g4.w + b4.w;

    size_t idx = (size_t)row * Cdim + t * 4;
    *(__half2*)(ohi + idx)     = __floats2half2_rn(o0, o1);
    *(__half2*)(ohi + idx + 2) = __floats2half2_rn(o2, o3);
}

// ----------------------- weight transpose (fp16 hi) ------------------------
__global__ __launch_bounds__(256) void wconv_kernel(
    const float* __restrict__ W, fp16* __restrict__ Whi, int K, int N)
{
    __shared__ float tile[32][33];
    int n0 = blockIdx.x * 32, k0 = blockIdx.y * 32;
    int tx = threadIdx.x & 31, ty = threadIdx.x >> 5;
    #pragma unroll
    for (int i = 0; i < 4; i++)
        tile[ty + i * 8][tx] = W[(size_t)(k0 + ty + i * 8) * N + n0 + tx];
    __syncthreads();
    #pragma unroll
    for (int i = 0; i < 4; i++) {
        int r = ty + i * 8;
        Whi[(size_t)(n0 + r) * K + k0 + tx] = __float2half_rn(tile[tx][r]);
    }
}

__global__ __launch_bounds__(256) void wconv2_kernel(
    const float* __restrict__ W1, const float* __restrict__ W2,
    fp16* __restrict__ D1, fp16* __restrict__ D2, int K, int N)
{
    const float* W = blockIdx.z ? W2 : W1;
    fp16* D = blockIdx.z ? D2 : D1;
    __shared__ float tile[32][33];
    int n0 = blockIdx.x * 32, k0 = blockIdx.y * 32;
    int tx = threadIdx.x & 31, ty = threadIdx.x >> 5;
    #pragma unroll
    for (int i = 0; i < 4; i++)
        tile[ty + i * 8][tx] = W[(size_t)(k0 + ty + i * 8) * N + n0 + tx];
    __syncthreads();
    #pragma unroll
    for (int i = 0; i < 4; i++) {
        int r = ty + i * 8;
        D[(size_t)(n0 + r) * K + k0 + tx] = __float2half_rn(tile[tx][r]);
    }
}

// --------------------------- mma.sync GEMM ---------------------------------
// C[M,N] = A_hi[M,K] @ B_hi^T,  B stored [N,K].  fp16, single pass.
// 128x256 CTA tile, BK=64, 8 warps (2m x 4n), 4-stage cp.async pipeline,
// one barrier/iter, intra-stage fragment double-buffering (k16 pipelining).
#define GF_BIAS  1
#define GF_RES   2
#define GF_GELU  4
#define GF_HI    16
#define GF_RES16 32

#define G_STRIDE_B 144u        // 64 fp16 (128B) + 16B pad
#define G_A_B      18432u      // 128 rows * 144B
#define G_B_B      36864u      // 256 rows * 144B
#define G_STAGE_B  55296u      // Ahi + Bhi
#define GEMM_SMEM  (4 * 55296) // 221184

__global__ __launch_bounds__(256, 1) void gemm_tc(
    const fp16* __restrict__ Ahi, const fp16* __restrict__ Bhi,
    const float* __restrict__ bias, const float* __restrict__ res,
    const fp16* __restrict__ resH,
    float* __restrict__ outF, fp16* __restrict__ outHi,
    int M, int N, int K, int flags)
{
    extern __shared__ char smem[];
    const uint32_t sb = smem_u32(smem);
    const int t = threadIdx.x, lane = t & 31, wid = t >> 5;
    const int bn = blockIdx.x, bm = blockIdx.y;
    const int wm = wid >> 2, wn = wid & 3;   // 2m x 4n warps

    const fp16* srcA = Ahi + (size_t)(bm * 128) * K;
    const fp16* srcB = Bhi + (size_t)(bn * 256) * K;

    auto load_stage = [&](int s) {
        uint32_t base = sb + (uint32_t)(s & 3) * G_STAGE_B;
        int k0 = s << 6;
        #pragma unroll
        for (int i = 0; i < 12; i++) {
            int idx = t + (i << 8);
            const fp16* src;
            uint32_t off;
            int cid;
            if (idx < 1024) { cid = idx;        src = srcA; off = 0; }
            else            { cid = idx - 1024; src = srcB; off = G_A_B; }
            int row = cid >> 3, c = cid & 7;
            cp16(base + off + (uint32_t)row * G_STRIDE_B + (uint32_t)c * 16u,
                 src + (size_t)row * K + k0 + c * 8);
        }
        CP_COMMIT();
    };

    float acc[4][8][4];
    #pragma unroll
    for (int mi = 0; mi < 4; mi++)
        #pragma unroll
        for (int ni = 0; ni < 8; ni++)
            #pragma unroll
            for (int j = 0; j < 4; j++) acc[mi][ni][j] = 0.f;

    load_stage(0);
    load_stage(1);
    load_stage(2);
    const int S = K >> 6;
    const uint32_t lrow = (uint32_t)(lane & 15);
    const uint32_t lc16 = (uint32_t)(lane >> 4) * 16u;
    const uint32_t aoff = ((uint32_t)(wm * 64) + lrow) * G_STRIDE_B + lc16;
    const uint32_t boff = ((uint32_t)(wn * 64) + lrow) * G_STRIDE_B + lc16;

    uint32_t ah[2][4][4], bf[2][4][4];

    for (int s = 0; s < S; s++) {
        if (s + 2 < S)      { CP_WAIT2(); }
        else if (s + 1 < S) { CP_WAIT1(); }
        else                { CP_WAIT0(); }
        __syncthreads();
        uint32_t base = sb + (uint32_t)(s & 3) * G_STAGE_B;

        // prime k16=0 fragments
        #pragma unroll
        for (int f = 0; f < 4; f++)
            ldsm4(ah[0][f], base + aoff + (uint32_t)f * 16u * G_STRIDE_B);
        #pragma unroll
        for (int g = 0; g < 4; g++)
            ldsm4(bf[0][g], base + G_A_B + boff + (uint32_t)g * 16u * G_STRIDE_B);

        #pragma unroll
        for (int k16 = 0; k16 < 4; k16++) {
            const int cur = k16 & 1, nxt = cur ^ 1;
            if (k16 < 3) {
                uint32_t ko = (uint32_t)(k16 + 1) * 32u;
                #pragma unroll
                for (int f = 0; f < 4; f++)
                    ldsm4(ah[nxt][f],
                          base + aoff + (uint32_t)f * 16u * G_STRIDE_B + ko);
                #pragma unroll
                for (int g = 0; g < 4; g++)
                    ldsm4(bf[nxt][g],
                          base + G_A_B + boff + (uint32_t)g * 16u * G_STRIDE_B + ko);
            }
            #pragma unroll
            for (int mi = 0; mi < 4; mi++)
                #pragma unroll
                for (int ni = 0; ni < 8; ni++)
                    mma16816(acc[mi][ni], ah[cur][mi],
                             bf[cur][ni >> 1][ni & 1],
                             bf[cur][ni >> 1][2 + (ni & 1)]);
        }
        if (s + 3 < S) load_stage(s + 3);
    }

    // ------------------------------ epilogue -------------------------------
    const int r0 = bm * 128 + wm * 64 + (lane >> 2);
    const int c0 = bn * 256 + wn * 64 + (lane & 3) * 2;
    #pragma unroll
    for (int mi = 0; mi < 4; mi++)
        #pragma unroll
        for (int rh = 0; rh < 2; rh++) {
            int row = r0 + mi * 16 + rh * 8;
            #pragma unroll
            for (int ni = 0; ni < 8; ni++) {
                int col = c0 + ni * 8;
                float v0 = acc[mi][ni][2 * rh];
                float v1 = acc[mi][ni][2 * rh + 1];
                if (flags & GF_BIAS) { v0 += bias[col]; v1 += bias[col + 1]; }
                if (flags & GF_GELU) {
                    v0 = 0.5f * v0 * (1.0f + erff(v0 * 0.70710678118654752f));
                    v1 = 0.5f * v1 * (1.0f + erff(v1 * 0.70710678118654752f));
                }
                if (flags & GF_RES) {
                    const float* rp = res + (size_t)row * N + col;
                    v0 += rp[0]; v1 += rp[1];
                }
                if (flags & GF_RES16) {
                    __half2 rv = *(const __half2*)(resH + (size_t)row * N + col);
                    v0 += __low2float(rv); v1 += __high2float(rv);
                }
                if (flags & GF_HI) {
                    *(__half2*)(outHi + (size_t)row * N + col) =
                        __floats2half2_rn(v0, v1);
                } else {
                    float2* po = (float2*)(outF + (size_t)row * N + col);
                    *po = make_float2(v0, v1);
                }
            }
        }
}

// --------------------- tensor-core flash attention -------------------------
#define A_STRIDE_B 144u
#define A_OP_B     9216u
#define A_STAGE_B  18432u
#define A_Q_B      9216u
#define ATTN_SMEM  (9216 + 2 * 18432)
#define KVS        (2 * Cdim)

__global__ __launch_bounds__(128) void attn_tc(
    const fp16* __restrict__ qhi, const fp16* __restrict__ kv,
    fp16* __restrict__ ohi)
{
    extern __shared__ char smem[];
    const uint32_t sb = smem_u32(smem);
    const int b = blockIdx.z, h = blockIdx.y, qt = blockIdx.x;
    const int t = threadIdx.x, lane = t & 31, wid = t >> 5;

    const size_t qrow0 = (size_t)(b * Nseq + qt * 64);
    const fp16* gq = qhi + qrow0 * Cdim + h * HD;
    const size_t krow0 = (size_t)b * Nseq;
    const fp16* gk = kv + krow0 * KVS + h * HD;
    const fp16* gv = kv + krow0 * KVS + Cdim + h * HD;

    #pragma unroll
    for (int i = 0; i < 4; i++) {
        int idx = t + (i << 7);
        int row = idx >> 3, c = idx & 7;
        cp16(sb + (uint32_t)row * A_STRIDE_B + (uint32_t)c * 16u,
             gq + (size_t)row * Cdim + c * 8);
    }
    CP_COMMIT();

    auto load_kv = [&](int kt) {
        uint32_t base = sb + A_Q_B + (uint32_t)(kt & 1) * A_STAGE_B;
        #pragma unroll
        for (int i = 0; i < 8; i++) {
            int idx = t + (i << 7);
            int op = idx >> 9, cid = idx & 511;
            int row = cid >> 3, c = cid & 7;
            const fp16* src = op ? gv : gk;
            cp16(base + (uint32_t)op * A_OP_B + (uint32_t)row * A_STRIDE_B
                      + (uint32_t)c * 16u,
                 src + (size_t)(kt * 64 + row) * KVS + c * 8);
        }
        CP_COMMIT();
    };

    load_kv(0);

    const uint32_t lrow = (uint32_t)(lane & 15);
    const uint32_t lc16 = (uint32_t)(lane >> 4) * 16u;

    uint32_t qh[4][4];
    float m_[2] = { -1e30f, -1e30f }, l_[2] = { 0.f, 0.f };
    float oacc[8][4];
    #pragma unroll
    for (int d = 0; d < 8; d++)
        #pragma unroll
        for (int j = 0; j < 4; j++) oacc[d][j] = 0.f;

    for (int kt = 0; kt < 16; kt++) {
        if (kt + 1 < 16) { load_kv(kt + 1); CP_WAIT1(); }
        else             { CP_WAIT0(); }
        __syncthreads();
        if (kt == 0) {
            uint32_t qoff = ((uint32_t)(wid * 16) + lrow) * A_STRIDE_B + lc16;
            #pragma unroll
            for (int k16 = 0; k16 < 4; k16++)
                ldsm4(qh[k16], sb + qoff + (uint32_t)k16 * 32u);
        }
        uint32_t base = sb + A_Q_B + (uint32_t)(kt & 1) * A_STAGE_B;

        // ---- S = Q K^T ----
        float sacc[8][4];
        #pragma unroll
        for (int ni = 0; ni < 8; ni++)
            #pragma unroll
            for (int j = 0; j < 4; j++) sacc[ni][j] = 0.f;
        uint32_t koff = lrow * A_STRIDE_B + lc16;
        #pragma unroll
        for (int k16 = 0; k16 < 4; k16++) {
            uint32_t kb[4][4];
            #pragma unroll
            for (int g = 0; g < 4; g++)
                ldsm4(kb[g], base + koff + (uint32_t)g * 16u * A_STRIDE_B
                             + (uint32_t)k16 * 32u);
            #pragma unroll
            for (int ni = 0; ni < 8; ni++)
                mma16816(sacc[ni], qh[k16],
                         kb[ni >> 1][ni & 1], kb[ni >> 1][2 + (ni & 1)]);
        }
        #pragma unroll
        for (int ni = 0; ni < 8; ni++)
            #pragma unroll
            for (int j = 0; j < 4; j++) sacc[ni][j] *= 0.125f;

        // ---- online softmax ----
        float corr[2];
        #pragma unroll
        for (int rh = 0; rh < 2; rh++) {
            float mx = m_[rh];
            #pragma unroll
            for (int ni = 0; ni < 8; ni++) {
                mx = fmaxf(mx, sacc[ni][2 * rh]);
                mx = fmaxf(mx, sacc[ni][2 * rh + 1]);
            }
            mx = fmaxf(mx, __shfl_xor_sync(0xffffffffu, mx, 1));
            mx = fmaxf(mx, __shfl_xor_sync(0xffffffffu, mx, 2));
            float c = __expf(m_[rh] - mx);
            m_[rh] = mx;
            float sum = 0.f;
            #pragma unroll
            for (int ni = 0; ni < 8; ni++) {
                float p0 = __expf(sacc[ni][2 * rh] - mx);
                float p1 = __expf(sacc[ni][2 * rh + 1] - mx);
                sacc[ni][2 * rh] = p0; sacc[ni][2 * rh + 1] = p1;
                sum += p0 + p1;
            }
            sum += __shfl_xor_sync(0xffffffffu, sum, 1);
            sum += __shfl_xor_sync(0xffffffffu, sum, 2);
            l_[rh] = l_[rh] * c + sum;
            corr[rh] = c;
        }
        #pragma unroll
        for (int d = 0; d < 8; d++) {
            oacc[d][0] *= corr[0]; oacc[d][1] *= corr[0];
            oacc[d][2] *= corr[1]; oacc[d][3] *= corr[1];
        }

        // ---- P -> fragments ----
        uint32_t pa[4][4];
        #pragma unroll
        for (int k16 = 0; k16 < 4; k16++) {
            pa[k16][0] = pack_h2(sacc[2*k16][0],   sacc[2*k16][1]);
            pa[k16][1] = pack_h2(sacc[2*k16][2],   sacc[2*k16][3]);
            pa[k16][2] = pack_h2(sacc[2*k16+1][0], sacc[2*k16+1][1]);
            pa[k16][3] = pack_h2(sacc[2*k16+1][2], sacc[2*k16+1][3]);
        }

        // ---- O += P V ----
        #pragma unroll
        for (int k16 = 0; k16 < 4; k16++) {
            uint32_t vh[4][4];
            uint32_t vrow = ((uint32_t)(k16 * 16) + lrow) * A_STRIDE_B + lc16;
            #pragma unroll
            for (int dblk = 0; dblk < 4; dblk++)
                ldsm4t(vh[dblk], base + A_OP_B + vrow + (uint32_t)dblk * 32u);
            #pragma unroll
            for (int dblk = 0; dblk < 4; dblk++)
                #pragma unroll
                for (int sub = 0; sub < 2; sub++)
                    mma16816(oacc[dblk * 2 + sub], pa[k16],
                             vh[dblk][2*sub], vh[dblk][2*sub+1]);
        }
        __syncthreads();
    }

    // ---- epilogue ----
    float inv[2] = { 1.0f / l_[0], 1.0f / l_[1] };
    const size_t orow = qrow0 + wid * 16 + (lane >> 2);
    const int c0 = h * HD + (lane & 3) * 2;
    #pragma unroll
    for (int di = 0; di < 8; di++)
        #pragma unroll
        for (int rh = 0; rh < 2; rh++) {
            size_t row = orow + rh * 8;
            int col = c0 + di * 8;
            float v0 = oacc[di][2 * rh]     * inv[rh];
            float v1 = oacc[di][2 * rh + 1] * inv[rh];
            *(__half2*)(ohi + row * Cdim + col) = __floats2half2_rn(v0, v1);
        }
}

// ------------------------------- launch ------------------------------------
extern "C" void kernel_launch(void* const* d_in, const int* in_sizes, int n_in,
                              void* d_out, int out_size)
{
    const float* x1     = (const float*)d_in[0];
    const float* x2     = (const float*)d_in[1];
    const float* x3     = (const float*)d_in[2];
    const float* ln11_g = (const float*)d_in[3];
    const float* ln11_b = (const float*)d_in[4];
    const float* ln12_g = (const float*)d_in[5];
    const float* ln12_b = (const float*)d_in[6];
    const float* ln21_g = (const float*)d_in[7];
    const float* ln21_b = (const float*)d_in[8];
    const float* ln23_g = (const float*)d_in[9];
    const float* ln23_b = (const float*)d_in[10];
    const float* ln2_g  = (const float*)d_in[11];
    const float* ln2_b  = (const float*)d_in[12];
    const float* a1_wq  = (const float*)d_in[13];
    const float* a1_wk  = (const float*)d_in[14];
    const float* a1_wv  = (const float*)d_in[15];
    const float* a1_wp  = (const float*)d_in[16];
    const float* a1_bp  = (const float*)d_in[17];
    const float* a2_wq  = (const float*)d_in[18];
    const float* a2_wk  = (const float*)d_in[19];
    const float* a2_wv  = (const float*)d_in[20];
    const float* a2_wp  = (const float*)d_in[21];
    const float* a2_bp  = (const float*)d_in[22];
    const float* fc1_w  = (const float*)d_in[23];
    const float* fc1_b  = (const float*)d_in[24];
    const float* fc2_w  = (const float*)d_in[25];
    const float* fc2_b  = (const float*)d_in[26];
    float* out = (float*)d_out;

    fp16 *wT_hi, *xA_hi, *xB_hi, *q_hi, *kv, *ao_hi, *h_hi, *res16;
    cudaGetSymbolAddress((void**)&wT_hi, g_wT_hi);
    cudaGetSymbolAddress((void**)&xA_hi, g_xA_hi);
    cudaGetSymbolAddress((void**)&xB_hi, g_xB_hi);
    cudaGetSymbolAddress((void**)&q_hi,  g_q_hi);
    cudaGetSymbolAddress((void**)&kv,    g_kv);
    cudaGetSymbolAddress((void**)&ao_hi, g_ao_hi);
    cudaGetSymbolAddress((void**)&h_hi,  g_h_hi);
    cudaGetSymbolAddress((void**)&res16, g_res16);

    cudaFuncSetAttribute(gemm_tc,
                         cudaFuncAttributeMaxDynamicSharedMemorySize, GEMM_SMEM);
    cudaFuncSetAttribute(attn_tc,
                         cudaFuncAttributeMaxDynamicSharedMemorySize, ATTN_SMEM);

    const size_t MEG = 1u << 20;
    dim3 wgC(Cdim / 32, Cdim / 32);
    dim3 wgC2(Cdim / 32, Cdim / 32, 2);
    dim3 gC(Cdim / 256, Mrows / 128);        // (4, 64)
    dim3 gKV(2 * Cdim / 256, Mrows / 128);   // (8, 64)
    dim3 gH(HidD / 256, Mrows / 128);        // (16, 64)
    dim3 ga(Nseq / 64, NH, Bsz);             // (16, 16, 8)

    // ---- branch 1 (launch index 3 == gemm_tc for the profiler) ----
    ln_kernel<<<Mrows, 256>>>(x1, ln11_g, ln11_b, xA_hi);                  // 0
    ln_kernel<<<Mrows, 256>>>(x2, ln12_g, ln12_b, xB_hi);                  // 1
    wconv_kernel<<<wgC, 256>>>(a1_wq, wT_hi + 0*MEG, Cdim, Cdim);          // 2
    gemm_tc<<<gC, 256, GEMM_SMEM>>>(xA_hi, wT_hi + 0*MEG,                  // 3 <- ncu
        nullptr, nullptr, nullptr, nullptr, q_hi, Mrows, Cdim, Cdim, GF_HI);
    wconv2_kernel<<<wgC2, 256>>>(a1_wk, a1_wv,
        wT_hi + 1*MEG, wT_hi + 2*MEG, Cdim, Cdim);                         // 4
    gemm_tc<<<gKV, 256, GEMM_SMEM>>>(xB_hi, wT_hi + 1*MEG,                 // 5
        nullptr, nullptr, nullptr, nullptr, kv, Mrows, 2 * Cdim, Cdim, GF_HI);
    attn_tc<<<ga, 128, ATTN_SMEM>>>(q_hi, kv, ao_hi);
    wconv_kernel<<<wgC, 256>>>(a1_wp, wT_hi + 3*MEG, Cdim, Cdim);
    gemm_tc<<<gC, 256, GEMM_SMEM>>>(ao_hi, wT_hi + 3*MEG,
        a1_bp, x1, nullptr, nullptr, res16, Mrows, Cdim, Cdim,
        GF_BIAS | GF_RES | GF_HI);

    // ---- remaining weight conversions ----
    wconv_kernel<<<wgC, 256>>>(a2_wq, wT_hi + 4*MEG, Cdim, Cdim);
    wconv2_kernel<<<wgC2, 256>>>(a2_wk, a2_wv,
        wT_hi + 5*MEG, wT_hi + 6*MEG, Cdim, Cdim);
    wconv_kernel<<<wgC, 256>>>(a2_wp, wT_hi + 7*MEG, Cdim, Cdim);
    wconv_kernel<<<dim3(HidD / 32, Cdim / 32), 256>>>(
        fc1_w, wT_hi + 8*MEG, Cdim, HidD);
    wconv_kernel<<<dim3(Cdim / 32, HidD / 32), 256>>>(
        fc2_w, wT_hi + 12*MEG, HidD, Cdim);

    // ---- branch 2 ----
    ln_kernel<<<Mrows, 256>>>(x1, ln21_g, ln21_b, xA_hi);
    ln_kernel<<<Mrows, 256>>>(x3, ln23_g, ln23_b, xB_hi);
    gemm_tc<<<gC, 256, GEMM_SMEM>>>(xA_hi, wT_hi + 4*MEG,
        nullptr, nullptr, nullptr, nullptr, q_hi, Mrows, Cdim, Cdim, GF_HI);
    gemm_tc<<<gKV, 256, GEMM_SMEM>>>(xB_hi, wT_hi + 5*MEG,
        nullptr, nullptr, nullptr, nullptr, kv, Mrows, 2 * Cdim, Cdim, GF_HI);
    attn_tc<<<ga, 128, ATTN_SMEM>>>(q_hi, kv, ao_hi);
    gemm_tc<<<gC, 256, GEMM_SMEM>>>(ao_hi, wT_hi + 7*MEG,
        a2_bp, nullptr, res16, nullptr, res16, Mrows, Cdim, Cdim,
        GF_BIAS | GF_RES16 | GF_HI);

    // ---- MLP ----
    ln16_kernel<<<Mrows, 256>>>(res16, ln2_g, ln2_b, xA_hi);
    gemm_tc<<<gH, 256, GEMM_SMEM>>>(xA_hi, wT_hi + 8*MEG,
        fc1_b, nullptr, nullptr, nullptr, h_hi, Mrows, HidD, Cdim,
        GF_BIAS | GF_GELU | GF_HI);
    gemm_tc<<<gC, 256, GEMM_SMEM>>>(h_hi, wT_hi + 12*MEG,
        fc2_b, nullptr, res16, out, nullptr, Mrows, Cdim, HidD,
        GF_BIAS | GF_RES16);
}

// round 15
// speedup vs baseline: 1.5034x; 1.0608x over previous
#include <cuda_runtime.h>
#include <cuda_fp16.h>
#include <math.h>
#include <stdint.h>

// ---------------------------------------------------------------------------
// CHI block on GB300 (sm_103 PTX => mma.sync HMMA path).
// R15: gemm_tc = 4-warp CTA (128 thr), warp tile 64x64, CTA tile 128x128,
// 3-stage cp.async, 2 CTAs/SM (register-file fits: ~190r x 128t x 2).
// Two independent barrier domains per SM keep the tensor pipe fed.
// ---------------------------------------------------------------------------

#define Bsz   8
#define Nseq  1024
#define Cdim  1024
#define HidD  4096
#define NH    16
#define HD    64
#define Mrows (Bsz * Nseq)           // 8192

typedef __half fp16;

// ---------------- scratch (static device globals; no allocs) ---------------
__device__ fp16 g_wT_hi[16u << 20];
__device__ fp16 g_xA_hi[(size_t)Mrows * Cdim];
__device__ fp16 g_xB_hi[(size_t)Mrows * Cdim];
__device__ fp16 g_q_hi [(size_t)Mrows * Cdim];
__device__ fp16 g_kv   [(size_t)Mrows * 2 * Cdim];
__device__ fp16 g_ao_hi[(size_t)Mrows * Cdim];
__device__ fp16 g_h_hi [(size_t)Mrows * HidD];
__device__ fp16 g_res16[(size_t)Mrows * Cdim];

// ------------------------------ PTX helpers --------------------------------
__device__ __forceinline__ uint32_t smem_u32(const void* p) {
    uint32_t a;
    asm("{ .reg .u64 t; cvta.to.shared.u64 t, %1; cvt.u32.u64 %0, t; }"
        : "=r"(a) : "l"(p));
    return a;
}

__device__ __forceinline__ void cp16(uint32_t dst, const void* src) {
    asm volatile("cp.async.cg.shared.global [%0], [%1], 16;\n"
                 :: "r"(dst), "l"(src) : "memory");
}
#define CP_COMMIT() asm volatile("cp.async.commit_group;\n" ::: "memory")
#define CP_WAIT1()  asm volatile("cp.async.wait_group 1;\n" ::: "memory")
#define CP_WAIT0()  asm volatile("cp.async.wait_group 0;\n" ::: "memory")

__device__ __forceinline__ void ldsm4(uint32_t (&r)[4], uint32_t addr) {
    asm volatile("ldmatrix.sync.aligned.m8n8.x4.shared.b16 {%0,%1,%2,%3}, [%4];"
        : "=r"(r[0]), "=r"(r[1]), "=r"(r[2]), "=r"(r[3]) : "r"(addr));
}
__device__ __forceinline__ void ldsm4t(uint32_t (&r)[4], uint32_t addr) {
    asm volatile("ldmatrix.sync.aligned.m8n8.x4.trans.shared.b16 {%0,%1,%2,%3}, [%4];"
        : "=r"(r[0]), "=r"(r[1]), "=r"(r[2]), "=r"(r[3]) : "r"(addr));
}

__device__ __forceinline__ void mma16816(float (&d)[4], const uint32_t (&a)[4],
                                         uint32_t b0, uint32_t b1) {
    asm volatile(
        "mma.sync.aligned.m16n8k16.row.col.f32.f16.f16.f32 "
        "{%0,%1,%2,%3}, {%4,%5,%6,%7}, {%8,%9}, {%0,%1,%2,%3};"
        : "+f"(d[0]), "+f"(d[1]), "+f"(d[2]), "+f"(d[3])
        : "r"(a[0]), "r"(a[1]), "r"(a[2]), "r"(a[3]), "r"(b0), "r"(b1));
}

__device__ __forceinline__ uint32_t pack_h2(float a, float b) {
    __half2 v = __floats2half2_rn(a, b);
    return *reinterpret_cast<uint32_t*>(&v);
}

// ------------------------------ LayerNorm ----------------------------------
__global__ __launch_bounds__(256) void ln_kernel(
    const float* __restrict__ x, const float* __restrict__ gma,
    const float* __restrict__ bta, fp16* __restrict__ ohi)
{
    int row = blockIdx.x;
    int t   = threadIdx.x;
    const float4* xr = (const float4*)(x + (size_t)row * Cdim);
    float4 v = xr[t];
    float s  = v.x + v.y + v.z + v.w;
    float s2 = v.x*v.x + v.y*v.y + v.z*v.z + v.w*v.w;

    __shared__ float sa[8], sb_[8];
    #pragma unroll
    for (int o = 16; o > 0; o >>= 1) {
        s  += __shfl_down_sync(0xffffffffu, s,  o);
        s2 += __shfl_down_sync(0xffffffffu, s2, o);
    }
    int w = t >> 5, l = t & 31;
    if (l == 0) { sa[w] = s; sb_[w] = s2; }
    __syncthreads();
    if (w == 0) {
        s  = (l < 8) ? sa[l] : 0.f;
        s2 = (l < 8) ? sb_[l] : 0.f;
        #pragma unroll
        for (int o = 4; o > 0; o >>= 1) {
            s  += __shfl_down_sync(0xffffffffu, s,  o);
            s2 += __shfl_down_sync(0xffffffffu, s2, o);
        }
        if (l == 0) { sa[0] = s; sb_[0] = s2; }
    }
    __syncthreads();
    float mean = sa[0] * (1.0f / Cdim);
    float var  = sb_[0] * (1.0f / Cdim) - mean * mean;
    float r    = rsqrtf(var + 1e-5f);

    float4 g4 = ((const float4*)gma)[t];
    float4 b4 = ((const float4*)bta)[t];
    float o0 = (v.x - mean) * r * g4.x + b4.x;
    float o1 = (v.y - mean) * r * g4.y + b4.y;
    float o2 = (v.z - mean) * r * g4.z + b4.z;
    float o3 = (v.w - mean) * r * g4.w + b4.w;

    size_t idx = (size_t)row * Cdim + t * 4;
    *(__half2*)(ohi + idx)     = __floats2half2_rn(o0, o1);
    *(__half2*)(ohi + idx + 2) = __floats2half2_rn(o2, o3);
}

// fp16-input LayerNorm
__global__ __launch_bounds__(256) void ln16_kernel(
    const fp16* __restrict__ x, const float* __restrict__ gma,
    const float* __restrict__ bta, fp16* __restrict__ ohi)
{
    int row = blockIdx.x;
    int t   = threadIdx.x;
    const __half2* xr = (const __half2*)(x + (size_t)row * Cdim);
    __half2 h0 = xr[2 * t], h1 = xr[2 * t + 1];
    float v0 = __low2float(h0), v1 = __high2float(h0);
    float v2 = __low2float(h1), v3 = __high2float(h1);
    float s  = v0 + v1 + v2 + v3;
    float s2 = v0*v0 + v1*v1 + v2*v2 + v3*v3;

    __shared__ float sa[8], sb_[8];
    #pragma unroll
    for (int o = 16; o > 0; o >>= 1) {
        s  += __shfl_down_sync(0xffffffffu, s,  o);
        s2 += __shfl_down_sync(0xffffffffu, s2, o);
    }
    int w = t >> 5, l = t & 31;
    if (l == 0) { sa[w] = s; sb_[w] = s2; }
    __syncthreads();
    if (w == 0) {
        s  = (l < 8) ? sa[l] : 0.f;
        s2 = (l < 8) ? sb_[l] : 0.f;
        #pragma unroll
        for (int o = 4; o > 0; o >>= 1) {
            s  += __shfl_down_sync(0xffffffffu, s,  o);
            s2 += __shfl_down_sync(0xffffffffu, s2, o);
        }
        if (l == 0) { sa[0] = s; sb_[0] = s2; }
    }
    __syncthreads();
    float mean = sa[0] * (1.0f / Cdim);
    float var  = sb_[0] * (1.0f / Cdim) - mean * mean;
    float r    = rsqrtf(var + 1e-5f);

    float4 g4 = ((const float4*)gma)[t];
    float4 b4 = ((const float4*)bta)[t];
    float o0 = (v0 - mean) * r * g4.x + b4.x;
    float o1 = (v1 - mean) * r * g4.y + b4.y;
    float o2 = (v2 - mean) * r * g4.z + b4.z;
    float o3 = (v3 - mean) * r * g4.w + b4.w;

    size_t idx = (size_t)row * Cdim + t * 4;
    *(__half2*)(ohi + idx)     = __floats2half2_rn(o0, o1);
    *(__half2*)(ohi + idx + 2) = __floats2half2_rn(o2, o3);
}

// ----------------------- weight transpose (fp16 hi) ------------------------
__global__ __launch_bounds__(256) void wconv_kernel(
    const float* __restrict__ W, fp16* __restrict__ Whi, int K, int N)
{
    __shared__ float tile[32][33];
    int n0 = blockIdx.x * 32, k0 = blockIdx.y * 32;
    int tx = threadIdx.x & 31, ty = threadIdx.x >> 5;
    #pragma unroll
    for (int i = 0; i < 4; i++)
        tile[ty + i * 8][tx] = W[(size_t)(k0 + ty + i * 8) * N + n0 + tx];
    __syncthreads();
    #pragma unroll
    for (int i = 0; i < 4; i++) {
        int r = ty + i * 8;
        Whi[(size_t)(n0 + r) * K + k0 + tx] = __float2half_rn(tile[tx][r]);
    }
}

__global__ __launch_bounds__(256) void wconv2_kernel(
    const float* __restrict__ W1, const float* __restrict__ W2,
    fp16* __restrict__ D1, fp16* __restrict__ D2, int K, int N)
{
    const float* W = blockIdx.z ? W2 : W1;
    fp16* D = blockIdx.z ? D2 : D1;
    __shared__ float tile[32][33];
    int n0 = blockIdx.x * 32, k0 = blockIdx.y * 32;
    int tx = threadIdx.x & 31, ty = threadIdx.x >> 5;
    #pragma unroll
    for (int i = 0; i < 4; i++)
        tile[ty + i * 8][tx] = W[(size_t)(k0 + ty + i * 8) * N + n0 + tx];
    __syncthreads();
    #pragma unroll
    for (int i = 0; i < 4; i++) {
        int r = ty + i * 8;
        D[(size_t)(n0 + r) * K + k0 + tx] = __float2half_rn(tile[tx][r]);
    }
}

// --------------------------- mma.sync GEMM ---------------------------------
// C[M,N] = A_hi[M,K] @ B_hi^T,  B stored [N,K].  fp16, single pass.
// 128x128 CTA tile, 128 threads = 4 warps (2m x 2n), warp tile 64x64,
// BK=64, 3-stage cp.async, one barrier/iter, 2 CTAs per SM.
#define GF_BIAS  1
#define GF_RES   2
#define GF_GELU  4
#define GF_HI    16
#define GF_RES16 32

#define G_STRIDE_B 144u        // 64 fp16 (128B) + 16B pad
#define G_A_B      18432u      // 128 rows * 144B
#define G_STAGE_B  36864u      // Ahi + Bhi (128 rows each)
#define GEMM_SMEM  (3 * 36864) // 110592 -> 2 CTAs/SM

__global__ __launch_bounds__(128, 2) void gemm_tc(
    const fp16* __restrict__ Ahi, const fp16* __restrict__ Bhi,
    const float* __restrict__ bias, const float* __restrict__ res,
    const fp16* __restrict__ resH,
    float* __restrict__ outF, fp16* __restrict__ outHi,
    int M, int N, int K, int flags)
{
    extern __shared__ char smem[];
    const uint32_t sb = smem_u32(smem);
    const int t = threadIdx.x, lane = t & 31, wid = t >> 5;
    const int bn = blockIdx.x, bm = blockIdx.y;
    const int wm = wid >> 1, wn = wid & 1;   // 2m x 2n warps, tile 64x64

    const fp16* srcA = Ahi + (size_t)(bm * 128) * K;
    const fp16* srcB = Bhi + (size_t)(bn * 128) * K;

    auto load_stage = [&](int s) {
        uint32_t base = sb + (uint32_t)(s % 3) * G_STAGE_B;
        int k0 = s << 6;
        #pragma unroll
        for (int i = 0; i < 16; i++) {
            int idx = t + (i << 7);
            const fp16* src;
            uint32_t off;
            int cid;
            if (idx < 1024) { cid = idx;        src = srcA; off = 0; }
            else            { cid = idx - 1024; src = srcB; off = G_A_B; }
            int row = cid >> 3, c = cid & 7;
            cp16(base + off + (uint32_t)row * G_STRIDE_B + (uint32_t)c * 16u,
                 src + (size_t)row * K + k0 + c * 8);
        }
        CP_COMMIT();
    };

    float acc[4][8][4];
    #pragma unroll
    for (int mi = 0; mi < 4; mi++)
        #pragma unroll
        for (int ni = 0; ni < 8; ni++)
            #pragma unroll
            for (int j = 0; j < 4; j++) acc[mi][ni][j] = 0.f;

    load_stage(0);
    load_stage(1);
    const int S = K >> 6;
    const uint32_t lrow = (uint32_t)(lane & 15);
    const uint32_t lc16 = (uint32_t)(lane >> 4) * 16u;
    const uint32_t aoff = ((uint32_t)(wm * 64) + lrow) * G_STRIDE_B + lc16;
    const uint32_t boff = ((uint32_t)(wn * 64) + lrow) * G_STRIDE_B + lc16;

    for (int s = 0; s < S; s++) {
        if (s + 1 < S) { CP_WAIT1(); }
        else           { CP_WAIT0(); }
        __syncthreads();
        uint32_t base = sb + (uint32_t)(s % 3) * G_STAGE_B;
        #pragma unroll
        for (int k16 = 0; k16 < 4; k16++) {
            uint32_t ko = (uint32_t)k16 * 32u;
            uint32_t ah[4][4], bf[4][4];
            #pragma unroll
            for (int f = 0; f < 4; f++)
                ldsm4(ah[f], base + aoff + (uint32_t)f * 16u * G_STRIDE_B + ko);
            #pragma unroll
            for (int g = 0; g < 4; g++)
                ldsm4(bf[g], base + G_A_B + boff + (uint32_t)g * 16u * G_STRIDE_B + ko);
            #pragma unroll
            for (int mi = 0; mi < 4; mi++)
                #pragma unroll
                for (int ni = 0; ni < 8; ni++)
                    mma16816(acc[mi][ni], ah[mi],
                             bf[ni >> 1][ni & 1], bf[ni >> 1][2 + (ni & 1)]);
        }
        if (s + 2 < S) load_stage(s + 2);
    }

    // ------------------------------ epilogue -------------------------------
    const int r0 = bm * 128 + wm * 64 + (lane >> 2);
    const int c0 = bn * 128 + wn * 64 + (lane & 3) * 2;
    #pragma unroll
    for (int mi = 0; mi < 4; mi++)
        #pragma unroll
        for (int rh = 0; rh < 2; rh++) {
            int row = r0 + mi * 16 + rh * 8;
            #pragma unroll
            for (int ni = 0; ni < 8; ni++) {
                int col = c0 + ni * 8;
                float v0 = acc[mi][ni][2 * rh];
                float v1 = acc[mi][ni][2 * rh + 1];
                if (flags & GF_BIAS) { v0 += bias[col]; v1 += bias[col + 1]; }
                if (flags & GF_GELU) {
                    v0 = 0.5f * v0 * (1.0f + erff(v0 * 0.70710678118654752f));
                    v1 = 0.5f * v1 * (1.0f + erff(v1 * 0.70710678118654752f));
                }
                if (flags & GF_RES) {
                    const float* rp = res + (size_t)row * N + col;
                    v0 += rp[0]; v1 += rp[1];
                }
                if (flags & GF_RES16) {
                    __half2 rv = *(const __half2*)(resH + (size_t)row * N + col);
                    v0 += __low2float(rv); v1 += __high2float(rv);
                }
                if (flags & GF_HI) {
                    *(__half2*)(outHi + (size_t)row * N + col) =
                        __floats2half2_rn(v0, v1);
                } else {
                    float2* po = (float2*)(outF + (size_t)row * N + col);
                    *po = make_float2(v0, v1);
                }
            }
        }
}

// --------------------- tensor-core flash attention -------------------------
#define A_STRIDE_B 144u
#define A_OP_B     9216u
#define A_STAGE_B  18432u
#define A_Q_B      9216u
#define ATTN_SMEM  (9216 + 2 * 18432)
#define KVS        (2 * Cdim)

__global__ __launch_bounds__(128) void attn_tc(
    const fp16* __restrict__ qhi, const fp16* __restrict__ kv,
    fp16* __restrict__ ohi)
{
    extern __shared__ char smem[];
    const uint32_t sb = smem_u32(smem);
    const int b = blockIdx.z, h = blockIdx.y, qt = blockIdx.x;
    const int t = threadIdx.x, lane = t & 31, wid = t >> 5;

    const size_t qrow0 = (size_t)(b * Nseq + qt * 64);
    const fp16* gq = qhi + qrow0 * Cdim + h * HD;
    const size_t krow0 = (size_t)b * Nseq;
    const fp16* gk = kv + krow0 * KVS + h * HD;
    const fp16* gv = kv + krow0 * KVS + Cdim + h * HD;

    #pragma unroll
    for (int i = 0; i < 4; i++) {
        int idx = t + (i << 7);
        int row = idx >> 3, c = idx & 7;
        cp16(sb + (uint32_t)row * A_STRIDE_B + (uint32_t)c * 16u,
             gq + (size_t)row * Cdim + c * 8);
    }
    CP_COMMIT();

    auto load_kv = [&](int kt) {
        uint32_t base = sb + A_Q_B + (uint32_t)(kt & 1) * A_STAGE_B;
        #pragma unroll
        for (int i = 0; i < 8; i++) {
            int idx = t + (i << 7);
            int op = idx >> 9, cid = idx & 511;
            int row = cid >> 3, c = cid & 7;
            const fp16* src = op ? gv : gk;
            cp16(base + (uint32_t)op * A_OP_B + (uint32_t)row * A_STRIDE_B
                      + (uint32_t)c * 16u,
                 src + (size_t)(kt * 64 + row) * KVS + c * 8);
        }
        CP_COMMIT();
    };

    load_kv(0);

    const uint32_t lrow = (uint32_t)(lane & 15);
    const uint32_t lc16 = (uint32_t)(lane >> 4) * 16u;

    uint32_t qh[4][4];
    float m_[2] = { -1e30f, -1e30f }, l_[2] = { 0.f, 0.f };
    float oacc[8][4];
    #pragma unroll
    for (int d = 0; d < 8; d++)
        #pragma unroll
        for (int j = 0; j < 4; j++) oacc[d][j] = 0.f;

    for (int kt = 0; kt < 16; kt++) {
        if (kt + 1 < 16) { load_kv(kt + 1); CP_WAIT1(); }
        else             { CP_WAIT0(); }
        __syncthreads();
        if (kt == 0) {
            uint32_t qoff = ((uint32_t)(wid * 16) + lrow) * A_STRIDE_B + lc16;
            #pragma unroll
            for (int k16 = 0; k16 < 4; k16++)
                ldsm4(qh[k16], sb + qoff + (uint32_t)k16 * 32u);
        }
        uint32_t base = sb + A_Q_B + (uint32_t)(kt & 1) * A_STAGE_B;

        // ---- S = Q K^T ----
        float sacc[8][4];
        #pragma unroll
        for (int ni = 0; ni < 8; ni++)
            #pragma unroll
            for (int j = 0; j < 4; j++) sacc[ni][j] = 0.f;
        uint32_t koff = lrow * A_STRIDE_B + lc16;
        #pragma unroll
        for (int k16 = 0; k16 < 4; k16++) {
            uint32_t kb[4][4];
            #pragma unroll
            for (int g = 0; g < 4; g++)
                ldsm4(kb[g], base + koff + (uint32_t)g * 16u * A_STRIDE_B
                             + (uint32_t)k16 * 32u);
            #pragma unroll
            for (int ni = 0; ni < 8; ni++)
                mma16816(sacc[ni], qh[k16],
                         kb[ni >> 1][ni & 1], kb[ni >> 1][2 + (ni & 1)]);
        }
        #pragma unroll
        for (int ni = 0; ni < 8; ni++)
            #pragma unroll
            for (int j = 0; j < 4; j++) sacc[ni][j] *= 0.125f;

        // ---- online softmax ----
        float corr[2];
        #pragma unroll
        for (int rh = 0; rh < 2; rh++) {
            float mx = m_[rh];
            #pragma unroll
            for (int ni = 0; ni < 8; ni++) {
                mx = fmaxf(mx, sacc[ni][2 * rh]);
                mx = fmaxf(mx, sacc[ni][2 * rh + 1]);
            }
            mx = fmaxf(mx, __shfl_xor_sync(0xffffffffu, mx, 1));
            mx = fmaxf(mx, __shfl_xor_sync(0xffffffffu, mx, 2));
            float c = __expf(m_[rh] - mx);
            m_[rh] = mx;
            float sum = 0.f;
            #pragma unroll
            for (int ni = 0; ni < 8; ni++) {
                float p0 = __expf(sacc[ni][2 * rh] - mx);
                float p1 = __expf(sacc[ni][2 * rh + 1] - mx);
                sacc[ni][2 * rh] = p0; sacc[ni][2 * rh + 1] = p1;
                sum += p0 + p1;
            }
            sum += __shfl_xor_sync(0xffffffffu, sum, 1);
            sum += __shfl_xor_sync(0xffffffffu, sum, 2);
            l_[rh] = l_[rh] * c + sum;
            corr[rh] = c;
        }
        #pragma unroll
        for (int d = 0; d < 8; d++) {
            oacc[d][0] *= corr[0]; oacc[d][1] *= corr[0];
            oacc[d][2] *= corr[1]; oacc[d][3] *= corr[1];
        }

        // ---- P -> fragments ----
        uint32_t pa[4][4];
        #pragma unroll
        for (int k16 = 0; k16 < 4; k16++) {
            pa[k16][0] = pack_h2(sacc[2*k16][0],   sacc[2*k16][1]);
            pa[k16][1] = pack_h2(sacc[2*k16][2],   sacc[2*k16][3]);
            pa[k16][2] = pack_h2(sacc[2*k16+1][0], sacc[2*k16+1][1]);
            pa[k16][3] = pack_h2(sacc[2*k16+1][2], sacc[2*k16+1][3]);
        }

        // ---- O += P V ----
        #pragma unroll
        for (int k16 = 0; k16 < 4; k16++) {
            uint32_t vh[4][4];
            uint32_t vrow = ((uint32_t)(k16 * 16) + lrow) * A_STRIDE_B + lc16;
            #pragma unroll
            for (int dblk = 0; dblk < 4; dblk++)
                ldsm4t(vh[dblk], base + A_OP_B + vrow + (uint32_t)dblk * 32u);
            #pragma unroll
            for (int dblk = 0; dblk < 4; dblk++)
                #pragma unroll
                for (int sub = 0; sub < 2; sub++)
                    mma16816(oacc[dblk * 2 + sub], pa[k16],
                             vh[dblk][2*sub], vh[dblk][2*sub+1]);
        }
        __syncthreads();
    }

    // ---- epilogue ----
    float inv[2] = { 1.0f / l_[0], 1.0f / l_[1] };
    const size_t orow = qrow0 + wid * 16 + (lane >> 2);
    const int c0 = h * HD + (lane & 3) * 2;
    #pragma unroll
    for (int di = 0; di < 8; di++)
        #pragma unroll
        for (int rh = 0; rh < 2; rh++) {
            size_t row = orow + rh * 8;
            int col = c0 + di * 8;
            float v0 = oacc[di][2 * rh]     * inv[rh];
            float v1 = oacc[di][2 * rh + 1] * inv[rh];
            *(__half2*)(ohi + row * Cdim + col) = __floats2half2_rn(v0, v1);
        }
}

// ------------------------------- launch ------------------------------------
extern "C" void kernel_launch(void* const* d_in, const int* in_sizes, int n_in,
                              void* d_out, int out_size)
{
    const float* x1     = (const float*)d_in[0];
    const float* x2     = (const float*)d_in[1];
    const float* x3     = (const float*)d_in[2];
    const float* ln11_g = (const float*)d_in[3];
    const float* ln11_b = (const float*)d_in[4];
    const float* ln12_g = (const float*)d_in[5];
    const float* ln12_b = (const float*)d_in[6];
    const float* ln21_g = (const float*)d_in[7];
    const float* ln21_b = (const float*)d_in[8];
    const float* ln23_g = (const float*)d_in[9];
    const float* ln23_b = (const float*)d_in[10];
    const float* ln2_g  = (const float*)d_in[11];
    const float* ln2_b  = (const float*)d_in[12];
    const float* a1_wq  = (const float*)d_in[13];
    const float* a1_wk  = (const float*)d_in[14];
    const float* a1_wv  = (const float*)d_in[15];
    const float* a1_wp  = (const float*)d_in[16];
    const float* a1_bp  = (const float*)d_in[17];
    const float* a2_wq  = (const float*)d_in[18];
    const float* a2_wk  = (const float*)d_in[19];
    const float* a2_wv  = (const float*)d_in[20];
    const float* a2_wp  = (const float*)d_in[21];
    const float* a2_bp  = (const float*)d_in[22];
    const float* fc1_w  = (const float*)d_in[23];
    const float* fc1_b  = (const float*)d_in[24];
    const float* fc2_w  = (const float*)d_in[25];
    const float* fc2_b  = (const float*)d_in[26];
    float* out = (float*)d_out;

    fp16 *wT_hi, *xA_hi, *xB_hi, *q_hi, *kv, *ao_hi, *h_hi, *res16;
    cudaGetSymbolAddress((void**)&wT_hi, g_wT_hi);
    cudaGetSymbolAddress((void**)&xA_hi, g_xA_hi);
    cudaGetSymbolAddress((void**)&xB_hi, g_xB_hi);
    cudaGetSymbolAddress((void**)&q_hi,  g_q_hi);
    cudaGetSymbolAddress((void**)&kv,    g_kv);
    cudaGetSymbolAddress((void**)&ao_hi, g_ao_hi);
    cudaGetSymbolAddress((void**)&h_hi,  g_h_hi);
    cudaGetSymbolAddress((void**)&res16, g_res16);

    cudaFuncSetAttribute(gemm_tc,
                         cudaFuncAttributeMaxDynamicSharedMemorySize, GEMM_SMEM);
    cudaFuncSetAttribute(attn_tc,
                         cudaFuncAttributeMaxDynamicSharedMemorySize, ATTN_SMEM);

    const size_t MEG = 1u << 20;
    dim3 wgC(Cdim / 32, Cdim / 32);
    dim3 wgC2(Cdim / 32, Cdim / 32, 2);
    dim3 gC(Cdim / 128, Mrows / 128);        // (8, 64)
    dim3 gKV(2 * Cdim / 128, Mrows / 128);   // (16, 64)
    dim3 gH(HidD / 128, Mrows / 128);        // (32, 64)
    dim3 ga(Nseq / 64, NH, Bsz);             // (16, 16, 8)

    // ---- branch 1 (launch index 3 == gemm_tc for the profiler) ----
    ln_kernel<<<Mrows, 256>>>(x1, ln11_g, ln11_b, xA_hi);                  // 0
    ln_kernel<<<Mrows, 256>>>(x2, ln12_g, ln12_b, xB_hi);                  // 1
    wconv_kernel<<<wgC, 256>>>(a1_wq, wT_hi + 0*MEG, Cdim, Cdim);          // 2
    gemm_tc<<<gC, 128, GEMM_SMEM>>>(xA_hi, wT_hi + 0*MEG,                  // 3 <- ncu
        nullptr, nullptr, nullptr, nullptr, q_hi, Mrows, Cdim, Cdim, GF_HI);
    wconv2_kernel<<<wgC2, 256>>>(a1_wk, a1_wv,
        wT_hi + 1*MEG, wT_hi + 2*MEG, Cdim, Cdim);                         // 4
    gemm_tc<<<gKV, 128, GEMM_SMEM>>>(xB_hi, wT_hi + 1*MEG,                 // 5
        nullptr, nullptr, nullptr, nullptr, kv, Mrows, 2 * Cdim, Cdim, GF_HI);
    attn_tc<<<ga, 128, ATTN_SMEM>>>(q_hi, kv, ao_hi);
    wconv_kernel<<<wgC, 256>>>(a1_wp, wT_hi + 3*MEG, Cdim, Cdim);
    gemm_tc<<<gC, 128, GEMM_SMEM>>>(ao_hi, wT_hi + 3*MEG,
        a1_bp, x1, nullptr, nullptr, res16, Mrows, Cdim, Cdim,
        GF_BIAS | GF_RES | GF_HI);

    // ---- remaining weight conversions ----
    wconv_kernel<<<wgC, 256>>>(a2_wq, wT_hi + 4*MEG, Cdim, Cdim);
    wconv2_kernel<<<wgC2, 256>>>(a2_wk, a2_wv,
        wT_hi + 5*MEG, wT_hi + 6*MEG, Cdim, Cdim);
    wconv_kernel<<<wgC, 256>>>(a2_wp, wT_hi + 7*MEG, Cdim, Cdim);
    wconv_kernel<<<dim3(HidD / 32, Cdim / 32), 256>>>(
        fc1_w, wT_hi + 8*MEG, Cdim, HidD);
    wconv_kernel<<<dim3(Cdim / 32, HidD / 32), 256>>>(
        fc2_w, wT_hi + 12*MEG, HidD, Cdim);

    // ---- branch 2 ----
    ln_kernel<<<Mrows, 256>>>(x1, ln21_g, ln21_b, xA_hi);
    ln_kernel<<<Mrows, 256>>>(x3, ln23_g, ln23_b, xB_hi);
    gemm_tc<<<gC, 128, GEMM_SMEM>>>(xA_hi, wT_hi + 4*MEG,
        nullptr, nullptr, nullptr, nullptr, q_hi, Mrows, Cdim, Cdim, GF_HI);
    gemm_tc<<<gKV, 128, GEMM_SMEM>>>(xB_hi, wT_hi + 5*MEG,
        nullptr, nullptr, nullptr, nullptr, kv, Mrows, 2 * Cdim, Cdim, GF_HI);
    attn_tc<<<ga, 128, ATTN_SMEM>>>(q_hi, kv, ao_hi);
    gemm_tc<<<gC, 128, GEMM_SMEM>>>(ao_hi, wT_hi + 7*MEG,
        a2_bp, nullptr, res16, nullptr, res16, Mrows, Cdim, Cdim,
        GF_BIAS | GF_RES16 | GF_HI);

    // ---- MLP ----
    ln16_kernel<<<Mrows, 256>>>(res16, ln2_g, ln2_b, xA_hi);
    gemm_tc<<<gH, 128, GEMM_SMEM>>>(xA_hi, wT_hi + 8*MEG,
        fc1_b, nullptr, nullptr, nullptr, h_hi, Mrows, HidD, Cdim,
        GF_BIAS | GF_GELU | GF_HI);
    gemm_tc<<<gC, 128, GEMM_SMEM>>>(h_hi, wT_hi + 12*MEG,
        fc2_b, nullptr, res16, out, nullptr, Mrows, Cdim, HidD,
        GF_BIAS | GF_RES16);
}